// round 1
// baseline (speedup 1.0000x reference)
#include <cuda_runtime.h>
#include <math_constants.h>

#define BB 4
#define TT 2048
#define EE 1024
#define HH 16
#define DD 64

// Scratch (device globals — no allocation allowed in kernel_launch)
__device__ float g_Q[BB*HH*TT*DD];
__device__ float g_K[BB*HH*TT*DD];
__device__ float g_V[BB*HH*TT*DD];
__device__ float g_ctx[BB*TT*EE];

// ---------------------------------------------------------------------------
// GEMM: C[m,n] = sum_k A[m,k] * W[n,k] + bias[n]   (A row-major MxK, W row-major NxK)
// mode 0: A = hidden, three weights (q/k/v) selected by blockIdx.x, epilogue
//         scatters to g_Q/g_K/g_V in [B,H,T,D] layout (Q scaled by 0.125).
// mode 1: A = g_ctx, W = out_w, plain epilogue to Cout (d_out).
// Tiling: BM=BN=128, BK=8, 256 threads, 8x8 microtile with split mapping.
// ---------------------------------------------------------------------------
__global__ __launch_bounds__(256, 2)
void gemm128(const float* __restrict__ Ain,
             const float* __restrict__ Wq, const float* __restrict__ bq,
             const float* __restrict__ Wk, const float* __restrict__ bk,
             const float* __restrict__ Wv, const float* __restrict__ bv,
             float* __restrict__ Cout, int mode)
{
    __shared__ float As[8][128];
    __shared__ float Bs[8][128];

    const int K = EE;
    const float* A = (mode == 0) ? Ain : g_ctx;

    const float* W;
    const float* bias;
    float* qkv = nullptr;
    float scale = 1.0f;
    int n0;
    if (mode == 0) {
        int mat = blockIdx.x >> 3;
        n0 = (blockIdx.x & 7) * 128;
        if (mat == 0)      { W = Wq; bias = bq; qkv = g_Q; scale = 0.125f; }
        else if (mat == 1) { W = Wk; bias = bk; qkv = g_K; }
        else               { W = Wv; bias = bv; qkv = g_V; }
    } else {
        n0 = blockIdx.x * 128;
        W = Wq; bias = bq;
    }
    const int m0 = blockIdx.y * 128;

    const int tid = threadIdx.x;
    const int tx = tid & 15;
    const int ty = tid >> 4;
    const int lr = tid >> 1;          // 0..127 (tile row for loads)
    const int lc = (tid & 1) * 4;     // 0 or 4 (k offset for loads)

    const float* Ap = A + (size_t)(m0 + lr) * K + lc;
    const float* Wp = W + (size_t)(n0 + lr) * K + lc;

    float acc[8][8];
    #pragma unroll
    for (int i = 0; i < 8; i++)
        #pragma unroll
        for (int j = 0; j < 8; j++) acc[i][j] = 0.f;

    for (int k0 = 0; k0 < K; k0 += 8) {
        float4 av = *(const float4*)(Ap + k0);
        float4 wv = *(const float4*)(Wp + k0);
        As[lc+0][lr] = av.x; As[lc+1][lr] = av.y;
        As[lc+2][lr] = av.z; As[lc+3][lr] = av.w;
        Bs[lc+0][lr] = wv.x; Bs[lc+1][lr] = wv.y;
        Bs[lc+2][lr] = wv.z; Bs[lc+3][lr] = wv.w;
        __syncthreads();
        #pragma unroll
        for (int kk = 0; kk < 8; kk++) {
            float ar[8], br[8];
            *(float4*)(ar)     = *(const float4*)&As[kk][ty*4];
            *(float4*)(ar + 4) = *(const float4*)&As[kk][64 + ty*4];
            *(float4*)(br)     = *(const float4*)&Bs[kk][tx*4];
            *(float4*)(br + 4) = *(const float4*)&Bs[kk][64 + tx*4];
            #pragma unroll
            for (int i = 0; i < 8; i++)
                #pragma unroll
                for (int j = 0; j < 8; j++)
                    acc[i][j] = fmaf(ar[i], br[j], acc[i][j]);
        }
        __syncthreads();
    }

    #pragma unroll
    for (int i = 0; i < 8; i++) {
        int row = m0 + ((i < 4) ? (ty*4 + i) : (64 + ty*4 + i - 4));
        #pragma unroll
        for (int g = 0; g < 2; g++) {
            int n = n0 + g*64 + tx*4;
            float4 bb = *(const float4*)(bias + n);
            int jb = g*4;
            float4 v;
            v.x = (acc[i][jb+0] + bb.x) * scale;
            v.y = (acc[i][jb+1] + bb.y) * scale;
            v.z = (acc[i][jb+2] + bb.z) * scale;
            v.w = (acc[i][jb+3] + bb.w) * scale;
            if (mode == 0) {
                int h = n >> 6, d = n & 63;
                int b = row >> 11, t = row & 2047;
                *(float4*)&qkv[(((size_t)(b*HH + h))*TT + t)*DD + d] = v;
            } else {
                *(float4*)&Cout[(size_t)row * EE + n] = v;
            }
        }
    }
}

// ---------------------------------------------------------------------------
// Flash attention, fp32. One block = (b,h) x 64 query rows. 256 threads (16x16).
// Score phase: rows = 4*ty+i, cols = tx+16*j (conflict-light LDS).
// PV phase:    rows = 4*ty+i, cols = 4*tx+cc (float4 V loads), P via shared.
// ---------------------------------------------------------------------------
#define ATTN_SMEM ((64*68*2 + 64*64*2) * 4)   // 67584 bytes

__global__ __launch_bounds__(256)
void attn_kernel()
{
    extern __shared__ float smp[];
    float* Qs = smp;                  // [64][68]
    float* Ks = smp + 64*68;          // [64][68]
    float* Vs = Ks  + 64*68;          // [64][64]
    float* Ps = Vs  + 64*64;          // [64][64]

    const int bh = blockIdx.y;        // 0..63
    const int q0 = blockIdx.x * 64;
    const float* Qg = g_Q + (size_t)bh*TT*DD + (size_t)q0*DD;
    const float* Kg = g_K + (size_t)bh*TT*DD;
    const float* Vg = g_V + (size_t)bh*TT*DD;

    const int tid = threadIdx.x;
    const int tx = tid & 15;
    const int ty = tid >> 4;

    // Load Q tile (64x64), already pre-scaled by 0.125 in the QKV GEMM.
    #pragma unroll
    for (int it = 0; it < 4; it++) {
        int idx = tid + it*256;
        int r = idx >> 4;
        int c = (idx & 15) * 4;
        *(float4*)&Qs[r*68 + c] = *(const float4*)(Qg + r*64 + c);
    }

    float O[4][4];
    float m[4], l[4];
    #pragma unroll
    for (int i = 0; i < 4; i++) {
        m[i] = -CUDART_INF_F;
        l[i] = 0.f;
        #pragma unroll
        for (int j = 0; j < 4; j++) O[i][j] = 0.f;
    }

    for (int kt = 0; kt < TT; kt += 64) {
        __syncthreads();   // prior PV done (and Qs ready on first iter)
        #pragma unroll
        for (int it = 0; it < 4; it++) {
            int idx = tid + it*256;
            int r = idx >> 4;
            int c = (idx & 15) * 4;
            *(float4*)&Ks[r*68 + c] = *(const float4*)(Kg + (size_t)(kt + r)*64 + c);
            *(float4*)&Vs[r*64 + c] = *(const float4*)(Vg + (size_t)(kt + r)*64 + c);
        }
        __syncthreads();

        // ---- scores: s[i][j] = Q[4ty+i] . K[tx+16j] ----
        float s[4][4];
        #pragma unroll
        for (int i = 0; i < 4; i++)
            #pragma unroll
            for (int j = 0; j < 4; j++) s[i][j] = 0.f;

        #pragma unroll
        for (int k4 = 0; k4 < 64; k4 += 4) {
            float4 qv[4], kv[4];
            #pragma unroll
            for (int i = 0; i < 4; i++)
                qv[i] = *(const float4*)&Qs[(ty*4 + i)*68 + k4];
            #pragma unroll
            for (int j = 0; j < 4; j++)
                kv[j] = *(const float4*)&Ks[(tx + 16*j)*68 + k4];
            #pragma unroll
            for (int i = 0; i < 4; i++)
                #pragma unroll
                for (int j = 0; j < 4; j++) {
                    s[i][j] = fmaf(qv[i].x, kv[j].x, s[i][j]);
                    s[i][j] = fmaf(qv[i].y, kv[j].y, s[i][j]);
                    s[i][j] = fmaf(qv[i].z, kv[j].z, s[i][j]);
                    s[i][j] = fmaf(qv[i].w, kv[j].w, s[i][j]);
                }
        }

        // ---- online softmax (row stats across the 16 tx lanes) ----
        #pragma unroll
        for (int i = 0; i < 4; i++) {
            float mt = fmaxf(fmaxf(s[i][0], s[i][1]), fmaxf(s[i][2], s[i][3]));
            #pragma unroll
            for (int off = 8; off; off >>= 1)
                mt = fmaxf(mt, __shfl_xor_sync(0xffffffffu, mt, off));
            float mnew = fmaxf(m[i], mt);
            float alpha = __expf(m[i] - mnew);
            float ls = 0.f;
            #pragma unroll
            for (int j = 0; j < 4; j++) {
                s[i][j] = __expf(s[i][j] - mnew);
                ls += s[i][j];
            }
            #pragma unroll
            for (int off = 8; off; off >>= 1)
                ls += __shfl_xor_sync(0xffffffffu, ls, off);
            l[i] = l[i]*alpha + ls;
            m[i] = mnew;
            #pragma unroll
            for (int j = 0; j < 4; j++) O[i][j] *= alpha;
            #pragma unroll
            for (int j = 0; j < 4; j++)
                Ps[(ty*4 + i)*64 + tx + 16*j] = s[i][j];
        }
        __syncthreads();

        // ---- PV: O[4ty+i][4tx+cc] += P[row][jk] * V[jk][4tx+cc] ----
        #pragma unroll
        for (int j4 = 0; j4 < 64; j4 += 4) {
            float4 pv[4];
            float vv[4][4];
            #pragma unroll
            for (int i = 0; i < 4; i++)
                pv[i] = *(const float4*)&Ps[(ty*4 + i)*64 + j4];
            #pragma unroll
            for (int jj = 0; jj < 4; jj++)
                *(float4*)vv[jj] = *(const float4*)&Vs[(j4 + jj)*64 + tx*4];
            #pragma unroll
            for (int i = 0; i < 4; i++)
                #pragma unroll
                for (int cc = 0; cc < 4; cc++) {
                    float o = O[i][cc];
                    o = fmaf(pv[i].x, vv[0][cc], o);
                    o = fmaf(pv[i].y, vv[1][cc], o);
                    o = fmaf(pv[i].z, vv[2][cc], o);
                    o = fmaf(pv[i].w, vv[3][cc], o);
                    O[i][cc] = o;
                }
        }
    }

    // ---- epilogue: ctx[B,T,E] = O / l ----
    const int b = bh >> 4, h = bh & 15;
    #pragma unroll
    for (int i = 0; i < 4; i++) {
        float inv = 1.0f / l[i];
        int t = q0 + ty*4 + i;
        float4 v;
        v.x = O[i][0] * inv;
        v.y = O[i][1] * inv;
        v.z = O[i][2] * inv;
        v.w = O[i][3] * inv;
        *(float4*)&g_ctx[((size_t)(b*TT + t))*EE + h*64 + tx*4] = v;
    }
}

// ---------------------------------------------------------------------------
extern "C" void kernel_launch(void* const* d_in, const int* in_sizes, int n_in,
                              void* d_out, int out_size)
{
    const float* hs    = (const float*)d_in[0];
    const float* q_w   = (const float*)d_in[1];
    const float* q_b   = (const float*)d_in[2];
    const float* k_w   = (const float*)d_in[3];
    const float* k_b   = (const float*)d_in[4];
    const float* v_w   = (const float*)d_in[5];
    const float* v_b   = (const float*)d_in[6];
    const float* out_w = (const float*)d_in[7];
    const float* out_b = (const float*)d_in[8];
    float* out = (float*)d_out;

    cudaFuncSetAttribute(attn_kernel,
                         cudaFuncAttributeMaxDynamicSharedMemorySize, ATTN_SMEM);

    // QKV projection (q/k/v fused into one grid: 24 n-tiles x 64 m-tiles)
    gemm128<<<dim3(24, 64), 256>>>(hs, q_w, q_b, k_w, k_b, v_w, v_b, nullptr, 0);
    // Flash attention: 32 query tiles x 64 (b,h) pairs
    attn_kernel<<<dim3(32, 64), 256, ATTN_SMEM>>>();
    // Output projection
    gemm128<<<dim3(8, 64), 256>>>(nullptr, out_w, out_b, nullptr, nullptr,
                                  nullptr, nullptr, out, 1);
}

// round 3
// speedup vs baseline: 1.0874x; 1.0874x over previous
#include <cuda_runtime.h>
#include <math_constants.h>
#include <cstdint>

#define BB 4
#define TT 2048
#define EE 1024
#define HH 16
#define DD 64

// Scratch (device globals — no allocation allowed in kernel_launch)
__device__ float g_Q[BB*HH*TT*DD];
__device__ float g_K[BB*HH*TT*DD];
__device__ float g_V[BB*HH*TT*DD];
__device__ float g_ctx[BB*TT*EE];

// ---------------------------------------------------------------------------
// tf32 helpers
// ---------------------------------------------------------------------------
__device__ __forceinline__ uint32_t f2tf32(float x) {
    uint32_t r;
    asm("cvt.rna.tf32.f32 %0, %1;" : "=r"(r) : "f"(x));
    return r;
}

__device__ __forceinline__ void mma_tf32(float c[4], const uint32_t a[4], const uint32_t b[2]) {
    asm volatile(
        "mma.sync.aligned.m16n8k8.row.col.f32.tf32.tf32.f32 "
        "{%0,%1,%2,%3}, {%4,%5,%6,%7}, {%8,%9}, {%0,%1,%2,%3};"
        : "+f"(c[0]), "+f"(c[1]), "+f"(c[2]), "+f"(c[3])
        : "r"(a[0]), "r"(a[1]), "r"(a[2]), "r"(a[3]), "r"(b[0]), "r"(b[1]));
}

// ---------------------------------------------------------------------------
// tf32 tensor-core GEMM: C[m,n] = sum_k A[m,k] * W[n,k] + bias[n]
// mode 0: A = hidden (fp32 gmem), 3 weights selected by blockIdx.x,
//         epilogue scatters to g_Q/g_K/g_V [B,H,T,D] (Q scaled 0.125).
// mode 1: A = g_ctx, W = out_w, epilogue to Cout row-major.
// Tile 128x128, BK=32, 256 threads (8 warps, 4m x 2n), warp tile 32x64.
// ---------------------------------------------------------------------------
#define PAD 36

__global__ void __launch_bounds__(256)
gemm_mma(const float* __restrict__ Ain,
         const float* __restrict__ Wq, const float* __restrict__ bq,
         const float* __restrict__ Wk, const float* __restrict__ bk,
         const float* __restrict__ Wv, const float* __restrict__ bv,
         float* __restrict__ Cout, int mode)
{
    __shared__ uint32_t As[128][PAD];
    __shared__ uint32_t Bs[128][PAD];

    const int K = EE;
    const float* A = (mode == 0) ? Ain : g_ctx;

    const float* W;
    const float* bias;
    float* qkv = nullptr;
    float scale = 1.0f;
    int n0;
    if (mode == 0) {
        int mat = blockIdx.x >> 3;
        n0 = (blockIdx.x & 7) * 128;
        if (mat == 0)      { W = Wq; bias = bq; qkv = g_Q; scale = 0.125f; }
        else if (mat == 1) { W = Wk; bias = bk; qkv = g_K; }
        else               { W = Wv; bias = bv; qkv = g_V; }
    } else {
        n0 = blockIdx.x * 128;
        W = Wq; bias = bq;
    }
    const int m0 = blockIdx.y * 128;

    const int tid  = threadIdx.x;
    const int wid  = tid >> 5;
    const int lane = tid & 31;
    const int grp  = lane >> 2;      // 0..7
    const int tig  = lane & 3;       // 0..3
    const int wm   = (wid & 3) * 32; // warp m offset in tile
    const int wn   = (wid >> 2) * 64;// warp n offset in tile

    float acc[2][8][4];
    #pragma unroll
    for (int i = 0; i < 2; i++)
        #pragma unroll
        for (int j = 0; j < 8; j++)
            #pragma unroll
            for (int q = 0; q < 4; q++) acc[i][j][q] = 0.f;

    for (int k0 = 0; k0 < K; k0 += 32) {
        // ---- fill smem (each thread: 4 float4 segs of A, 4 of B), tf32-round ----
        #pragma unroll
        for (int it = 0; it < 4; it++) {
            int idx = tid + it * 256;     // 0..1023
            int r = idx >> 3;             // row 0..127
            int s = (idx & 7) * 4;        // col 0..28
            float4 av = *(const float4*)(A + (size_t)(m0 + r) * K + k0 + s);
            float4 wv = *(const float4*)(W + (size_t)(n0 + r) * K + k0 + s);
            As[r][s+0] = f2tf32(av.x); As[r][s+1] = f2tf32(av.y);
            As[r][s+2] = f2tf32(av.z); As[r][s+3] = f2tf32(av.w);
            Bs[r][s+0] = f2tf32(wv.x); Bs[r][s+1] = f2tf32(wv.y);
            Bs[r][s+2] = f2tf32(wv.z); Bs[r][s+3] = f2tf32(wv.w);
        }
        __syncthreads();

        // ---- 4 k8 steps ----
        #pragma unroll
        for (int kk = 0; kk < 4; kk++) {
            const int kb = kk * 8;
            uint32_t a[2][4], b[8][2];
            #pragma unroll
            for (int mt = 0; mt < 2; mt++) {
                a[mt][0] = As[wm + mt*16 + grp    ][kb + tig];
                a[mt][1] = As[wm + mt*16 + grp + 8][kb + tig];
                a[mt][2] = As[wm + mt*16 + grp    ][kb + tig + 4];
                a[mt][3] = As[wm + mt*16 + grp + 8][kb + tig + 4];
            }
            #pragma unroll
            for (int nt = 0; nt < 8; nt++) {
                b[nt][0] = Bs[wn + nt*8 + grp][kb + tig];
                b[nt][1] = Bs[wn + nt*8 + grp][kb + tig + 4];
            }
            #pragma unroll
            for (int mt = 0; mt < 2; mt++)
                #pragma unroll
                for (int nt = 0; nt < 8; nt++)
                    mma_tf32(acc[mt][nt], a[mt], b[nt]);
        }
        __syncthreads();
    }

    // ---- epilogue ----
    #pragma unroll
    for (int mt = 0; mt < 2; mt++) {
        #pragma unroll
        for (int half = 0; half < 2; half++) {
            const int row = m0 + wm + mt*16 + grp + half*8;
            #pragma unroll
            for (int nt = 0; nt < 8; nt++) {
                const int col = n0 + wn + nt*8 + tig*2;
                float c0 = acc[mt][nt][half*2 + 0];
                float c1 = acc[mt][nt][half*2 + 1];
                float2 v;
                v.x = (c0 + bias[col])     * scale;
                v.y = (c1 + bias[col + 1]) * scale;
                if (mode == 0) {
                    int h = col >> 6, d = col & 63;
                    int b_ = row >> 11, t = row & 2047;
                    *(float2*)&qkv[(((size_t)(b_*HH + h))*TT + t)*DD + d] = v;
                } else {
                    *(float2*)&Cout[(size_t)row * EE + col] = v;
                }
            }
        }
    }
}

// ---------------------------------------------------------------------------
// Flash attention, fp32 SIMT (unchanged from Round 1).
// ---------------------------------------------------------------------------
#define ATTN_SMEM ((64*68*2 + 64*64*2) * 4)

__global__ __launch_bounds__(256)
void attn_kernel()
{
    extern __shared__ float smp[];
    float* Qs = smp;                  // [64][68]
    float* Ks = smp + 64*68;          // [64][68]
    float* Vs = Ks  + 64*68;          // [64][64]
    float* Ps = Vs  + 64*64;          // [64][64]

    const int bh = blockIdx.y;
    const int q0 = blockIdx.x * 64;
    const float* Qg = g_Q + (size_t)bh*TT*DD + (size_t)q0*DD;
    const float* Kg = g_K + (size_t)bh*TT*DD;
    const float* Vg = g_V + (size_t)bh*TT*DD;

    const int tid = threadIdx.x;
    const int tx = tid & 15;
    const int ty = tid >> 4;

    #pragma unroll
    for (int it = 0; it < 4; it++) {
        int idx = tid + it*256;
        int r = idx >> 4;
        int c = (idx & 15) * 4;
        *(float4*)&Qs[r*68 + c] = *(const float4*)(Qg + r*64 + c);
    }

    float O[4][4];
    float m[4], l[4];
    #pragma unroll
    for (int i = 0; i < 4; i++) {
        m[i] = -CUDART_INF_F;
        l[i] = 0.f;
        #pragma unroll
        for (int j = 0; j < 4; j++) O[i][j] = 0.f;
    }

    for (int kt = 0; kt < TT; kt += 64) {
        __syncthreads();
        #pragma unroll
        for (int it = 0; it < 4; it++) {
            int idx = tid + it*256;
            int r = idx >> 4;
            int c = (idx & 15) * 4;
            *(float4*)&Ks[r*68 + c] = *(const float4*)(Kg + (size_t)(kt + r)*64 + c);
            *(float4*)&Vs[r*64 + c] = *(const float4*)(Vg + (size_t)(kt + r)*64 + c);
        }
        __syncthreads();

        float s[4][4];
        #pragma unroll
        for (int i = 0; i < 4; i++)
            #pragma unroll
            for (int j = 0; j < 4; j++) s[i][j] = 0.f;

        #pragma unroll
        for (int k4 = 0; k4 < 64; k4 += 4) {
            float4 qv[4], kv[4];
            #pragma unroll
            for (int i = 0; i < 4; i++)
                qv[i] = *(const float4*)&Qs[(ty*4 + i)*68 + k4];
            #pragma unroll
            for (int j = 0; j < 4; j++)
                kv[j] = *(const float4*)&Ks[(tx + 16*j)*68 + k4];
            #pragma unroll
            for (int i = 0; i < 4; i++)
                #pragma unroll
                for (int j = 0; j < 4; j++) {
                    s[i][j] = fmaf(qv[i].x, kv[j].x, s[i][j]);
                    s[i][j] = fmaf(qv[i].y, kv[j].y, s[i][j]);
                    s[i][j] = fmaf(qv[i].z, kv[j].z, s[i][j]);
                    s[i][j] = fmaf(qv[i].w, kv[j].w, s[i][j]);
                }
        }

        #pragma unroll
        for (int i = 0; i < 4; i++) {
            float mt = fmaxf(fmaxf(s[i][0], s[i][1]), fmaxf(s[i][2], s[i][3]));
            #pragma unroll
            for (int off = 8; off; off >>= 1)
                mt = fmaxf(mt, __shfl_xor_sync(0xffffffffu, mt, off));
            float mnew = fmaxf(m[i], mt);
            float alpha = __expf(m[i] - mnew);
            float ls = 0.f;
            #pragma unroll
            for (int j = 0; j < 4; j++) {
                s[i][j] = __expf(s[i][j] - mnew);
                ls += s[i][j];
            }
            #pragma unroll
            for (int off = 8; off; off >>= 1)
                ls += __shfl_xor_sync(0xffffffffu, ls, off);
            l[i] = l[i]*alpha + ls;
            m[i] = mnew;
            #pragma unroll
            for (int j = 0; j < 4; j++) O[i][j] *= alpha;
            #pragma unroll
            for (int j = 0; j < 4; j++)
                Ps[(ty*4 + i)*64 + tx + 16*j] = s[i][j];
        }
        __syncthreads();

        #pragma unroll
        for (int j4 = 0; j4 < 64; j4 += 4) {
            float4 pv[4];
            float vv[4][4];
            #pragma unroll
            for (int i = 0; i < 4; i++)
                pv[i] = *(const float4*)&Ps[(ty*4 + i)*64 + j4];
            #pragma unroll
            for (int jj = 0; jj < 4; jj++)
                *(float4*)vv[jj] = *(const float4*)&Vs[(j4 + jj)*64 + tx*4];
            #pragma unroll
            for (int i = 0; i < 4; i++)
                #pragma unroll
                for (int cc = 0; cc < 4; cc++) {
                    float o = O[i][cc];
                    o = fmaf(pv[i].x, vv[0][cc], o);
                    o = fmaf(pv[i].y, vv[1][cc], o);
                    o = fmaf(pv[i].z, vv[2][cc], o);
                    o = fmaf(pv[i].w, vv[3][cc], o);
                    O[i][cc] = o;
                }
        }
    }

    const int b = bh >> 4, h = bh & 15;
    #pragma unroll
    for (int i = 0; i < 4; i++) {
        float inv = 1.0f / l[i];
        int t = q0 + ty*4 + i;
        float4 v;
        v.x = O[i][0] * inv;
        v.y = O[i][1] * inv;
        v.z = O[i][2] * inv;
        v.w = O[i][3] * inv;
        *(float4*)&g_ctx[((size_t)(b*TT + t))*EE + h*64 + tx*4] = v;
    }
}

// ---------------------------------------------------------------------------
extern "C" void kernel_launch(void* const* d_in, const int* in_sizes, int n_in,
                              void* d_out, int out_size)
{
    const float* hs    = (const float*)d_in[0];
    const float* q_w   = (const float*)d_in[1];
    const float* q_b   = (const float*)d_in[2];
    const float* k_w   = (const float*)d_in[3];
    const float* k_b   = (const float*)d_in[4];
    const float* v_w   = (const float*)d_in[5];
    const float* v_b   = (const float*)d_in[6];
    const float* out_w = (const float*)d_in[7];
    const float* out_b = (const float*)d_in[8];
    float* out = (float*)d_out;

    cudaFuncSetAttribute(attn_kernel,
                         cudaFuncAttributeMaxDynamicSharedMemorySize, ATTN_SMEM);

    // QKV projection (tf32 tensor cores)
    gemm_mma<<<dim3(24, 64), 256>>>(hs, q_w, q_b, k_w, k_b, v_w, v_b, nullptr, 0);
    // Flash attention (fp32 SIMT)
    attn_kernel<<<dim3(32, 64), 256, ATTN_SMEM>>>();
    // Output projection (tf32 tensor cores)
    gemm_mma<<<dim3(8, 64), 256>>>(nullptr, out_w, out_b, nullptr, nullptr,
                                   nullptr, nullptr, out, 1);
}

// round 5
// speedup vs baseline: 2.7710x; 2.5483x over previous
#include <cuda_runtime.h>
#include <math_constants.h>
#include <cstdint>

#define BB 4
#define TT 2048
#define EE 1024
#define HH 16
#define DD 64

// Scratch (device globals — no allocation allowed in kernel_launch)
__device__ float g_Q[BB*HH*TT*DD];     // [b,h,t,d]  tf32-rounded, pre-scaled 0.125
__device__ float g_K[BB*HH*TT*DD];     // [b,h,t,d]  tf32-rounded
__device__ float g_Vt[BB*HH*DD*TT];    // [b,h,d,t]  tf32-rounded, TRANSPOSED
__device__ float g_ctx[BB*TT*EE];

// ---------------------------------------------------------------------------
// helpers
// ---------------------------------------------------------------------------
__device__ __forceinline__ uint32_t f2tf32(float x) {
    uint32_t r;
    asm("cvt.rna.tf32.f32 %0, %1;" : "=r"(r) : "f"(x));
    return r;
}
__device__ __forceinline__ float rtf(float x) { return __uint_as_float(f2tf32(x)); }

__device__ __forceinline__ void mma_tf32(float c[4], const uint32_t a[4], const uint32_t b[2]) {
    asm volatile(
        "mma.sync.aligned.m16n8k8.row.col.f32.tf32.tf32.f32 "
        "{%0,%1,%2,%3}, {%4,%5,%6,%7}, {%8,%9}, {%0,%1,%2,%3};"
        : "+f"(c[0]), "+f"(c[1]), "+f"(c[2]), "+f"(c[3])
        : "r"(a[0]), "r"(a[1]), "r"(a[2]), "r"(a[3]), "r"(b[0]), "r"(b[1]));
}

// exp on the FMA pipe (no MUFU): e^x = 2^(x*log2e); poly for 2^f, f in [-0.5,0.5]
__device__ __forceinline__ float fexp(float x) {
    x = fmaxf(x, -80.0f);
    float y = x * 1.4426950408889634f;
    float r = rintf(y);
    float f = y - r;
    float p = 0.0013333558146428443f;           // ln2^5/120
    p = fmaf(p, f, 0.009618129107628477f);      // ln2^4/24
    p = fmaf(p, f, 0.05550410866482158f);       // ln2^3/6
    p = fmaf(p, f, 0.2402265069591007f);        // ln2^2/2
    p = fmaf(p, f, 0.6931471805599453f);        // ln2
    p = fmaf(p, f, 1.0f);
    return p * __int_as_float(((int)r + 127) << 23);
}

// ---------------------------------------------------------------------------
// tf32 tensor-core GEMM (epilogue emits rounded Q/K and rounded+transposed V).
// ---------------------------------------------------------------------------
#define PAD 36

__global__ void __launch_bounds__(256)
gemm_mma(const float* __restrict__ Ain,
         const float* __restrict__ Wq, const float* __restrict__ bq,
         const float* __restrict__ Wk, const float* __restrict__ bk,
         const float* __restrict__ Wv, const float* __restrict__ bv,
         float* __restrict__ Cout, int mode)
{
    __shared__ uint32_t As[128][PAD];
    __shared__ uint32_t Bs[128][PAD];

    const int K = EE;
    const float* A = (mode == 0) ? Ain : g_ctx;

    const float* W;
    const float* bias;
    float* qkv = nullptr;
    float scale = 1.0f;
    int n0;
    int mat = 0;
    if (mode == 0) {
        mat = blockIdx.x >> 3;
        n0 = (blockIdx.x & 7) * 128;
        if (mat == 0)      { W = Wq; bias = bq; qkv = g_Q; scale = 0.125f; }
        else if (mat == 1) { W = Wk; bias = bk; qkv = g_K; }
        else               { W = Wv; bias = bv; }
    } else {
        n0 = blockIdx.x * 128;
        W = Wq; bias = bq;
    }
    const int m0 = blockIdx.y * 128;

    const int tid  = threadIdx.x;
    const int wid  = tid >> 5;
    const int lane = tid & 31;
    const int grp  = lane >> 2;
    const int tig  = lane & 3;
    const int wm   = (wid & 3) * 32;
    const int wn   = (wid >> 2) * 64;

    float acc[2][8][4];
    #pragma unroll
    for (int i = 0; i < 2; i++)
        #pragma unroll
        for (int j = 0; j < 8; j++)
            #pragma unroll
            for (int q = 0; q < 4; q++) acc[i][j][q] = 0.f;

    for (int k0 = 0; k0 < K; k0 += 32) {
        #pragma unroll
        for (int it = 0; it < 4; it++) {
            int idx = tid + it * 256;
            int r = idx >> 3;
            int s = (idx & 7) * 4;
            float4 av = *(const float4*)(A + (size_t)(m0 + r) * K + k0 + s);
            float4 wv = *(const float4*)(W + (size_t)(n0 + r) * K + k0 + s);
            As[r][s+0] = f2tf32(av.x); As[r][s+1] = f2tf32(av.y);
            As[r][s+2] = f2tf32(av.z); As[r][s+3] = f2tf32(av.w);
            Bs[r][s+0] = f2tf32(wv.x); Bs[r][s+1] = f2tf32(wv.y);
            Bs[r][s+2] = f2tf32(wv.z); Bs[r][s+3] = f2tf32(wv.w);
        }
        __syncthreads();

        #pragma unroll
        for (int kk = 0; kk < 4; kk++) {
            const int kb = kk * 8;
            uint32_t a[2][4], b[8][2];
            #pragma unroll
            for (int mt = 0; mt < 2; mt++) {
                a[mt][0] = As[wm + mt*16 + grp    ][kb + tig];
                a[mt][1] = As[wm + mt*16 + grp + 8][kb + tig];
                a[mt][2] = As[wm + mt*16 + grp    ][kb + tig + 4];
                a[mt][3] = As[wm + mt*16 + grp + 8][kb + tig + 4];
            }
            #pragma unroll
            for (int nt = 0; nt < 8; nt++) {
                b[nt][0] = Bs[wn + nt*8 + grp][kb + tig];
                b[nt][1] = Bs[wn + nt*8 + grp][kb + tig + 4];
            }
            #pragma unroll
            for (int mt = 0; mt < 2; mt++)
                #pragma unroll
                for (int nt = 0; nt < 8; nt++)
                    mma_tf32(acc[mt][nt], a[mt], b[nt]);
        }
        __syncthreads();
    }

    #pragma unroll
    for (int mt = 0; mt < 2; mt++) {
        #pragma unroll
        for (int half = 0; half < 2; half++) {
            const int row = m0 + wm + mt*16 + grp + half*8;
            #pragma unroll
            for (int nt = 0; nt < 8; nt++) {
                const int col = n0 + wn + nt*8 + tig*2;
                float c0 = (acc[mt][nt][half*2 + 0] + bias[col])     * scale;
                float c1 = (acc[mt][nt][half*2 + 1] + bias[col + 1]) * scale;
                if (mode == 0) {
                    int h = col >> 6, d = col & 63;
                    int b_ = row >> 11, t = row & 2047;
                    if (mat == 2) {
                        size_t base = (((size_t)(b_*HH + h))*DD + d)*TT + t;
                        g_Vt[base]      = rtf(c0);
                        g_Vt[base + TT] = rtf(c1);
                    } else {
                        float2 v; v.x = rtf(c0); v.y = rtf(c1);
                        *(float2*)&qkv[(((size_t)(b_*HH + h))*TT + t)*DD + d] = v;
                    }
                } else {
                    float2 v; v.x = c0; v.y = c1;
                    *(float2*)&Cout[(size_t)row * EE + col] = v;
                }
            }
        }
    }
}

// ---------------------------------------------------------------------------
// Flash attention on tf32 tensor cores.
// Block = 128 threads (4 warps); each warp owns 16 query rows of a 64-row tile.
// ---------------------------------------------------------------------------
#define APAD 68
#define ATTN_SMEM (3 * 64 * APAD * 4)   // Ks + Vt + Ps = 52224 B

__global__ void __launch_bounds__(128)
attn_mma()
{
    extern __shared__ float sm[];
    float* Ks = sm;                 // [64][APAD]  rows = s, cols = d
    float* Vt = sm + 64*APAD;       // [64][APAD]  rows = d, cols = s
    float* Ps = Vt + 64*APAD;       // [64][APAD]  rows = q (warp-private 16)

    const int bh = blockIdx.y;
    const int q0 = blockIdx.x * 64;
    const float* Qg = g_Q  + (size_t)bh*TT*DD;
    const float* Kg = g_K  + (size_t)bh*TT*DD;
    const float* Vg = g_Vt + (size_t)bh*DD*TT;

    const int tid  = threadIdx.x;
    const int lane = tid & 31;
    const int w    = tid >> 5;
    const int grp  = lane >> 2;
    const int tig  = lane & 3;
    const int r0   = q0 + w*16 + grp;
    const int r1   = r0 + 8;

    // Q fragments (pre-rounded tf32 in gmem)
    uint32_t qa[8][4];
    #pragma unroll
    for (int kk = 0; kk < 8; kk++) {
        qa[kk][0] = __float_as_uint(Qg[(size_t)r0*DD + kk*8 + tig]);
        qa[kk][1] = __float_as_uint(Qg[(size_t)r1*DD + kk*8 + tig]);
        qa[kk][2] = __float_as_uint(Qg[(size_t)r0*DD + kk*8 + tig + 4]);
        qa[kk][3] = __float_as_uint(Qg[(size_t)r1*DD + kk*8 + tig + 4]);
    }

    float o[8][4];
    #pragma unroll
    for (int nt = 0; nt < 8; nt++)
        #pragma unroll
        for (int q = 0; q < 4; q++) o[nt][q] = 0.f;
    float m0 = -CUDART_INF_F, m1 = -CUDART_INF_F, l0 = 0.f, l1 = 0.f;

    for (int kt = 0; kt < TT; kt += 64) {
        __syncthreads();
        // load K tile and V^T tile: 64 rows x 16 float4 each (1024 slots, 8 iters)
        #pragma unroll
        for (int it = 0; it < 8; it++) {
            int idx = tid + it*128;        // 0..1023
            int r = idx >> 4;              // row 0..63
            int c = (idx & 15) * 4;        // col 0..60
            *(float4*)&Ks[r*APAD + c] = *(const float4*)&Kg[(size_t)(kt + r)*DD + c];
            *(float4*)&Vt[r*APAD + c] = *(const float4*)&Vg[(size_t)r*TT + kt + c];
        }
        __syncthreads();

        // ---- S = Q K^T ----
        float s[8][4];
        #pragma unroll
        for (int nt = 0; nt < 8; nt++)
            #pragma unroll
            for (int q = 0; q < 4; q++) s[nt][q] = 0.f;

        #pragma unroll
        for (int kk = 0; kk < 8; kk++) {
            #pragma unroll
            for (int nt = 0; nt < 8; nt++) {
                uint32_t b[2];
                b[0] = __float_as_uint(Ks[(nt*8 + grp)*APAD + kk*8 + tig]);
                b[1] = __float_as_uint(Ks[(nt*8 + grp)*APAD + kk*8 + tig + 4]);
                mma_tf32(s[nt], qa[kk], b);
            }
        }

        // ---- online softmax ----
        float mx0 = -CUDART_INF_F, mx1 = -CUDART_INF_F;
        #pragma unroll
        for (int nt = 0; nt < 8; nt++) {
            mx0 = fmaxf(mx0, fmaxf(s[nt][0], s[nt][1]));
            mx1 = fmaxf(mx1, fmaxf(s[nt][2], s[nt][3]));
        }
        #pragma unroll
        for (int off = 1; off <= 2; off <<= 1) {
            mx0 = fmaxf(mx0, __shfl_xor_sync(0xffffffffu, mx0, off));
            mx1 = fmaxf(mx1, __shfl_xor_sync(0xffffffffu, mx1, off));
        }
        float mn0 = fmaxf(m0, mx0), mn1 = fmaxf(m1, mx1);
        float a0 = fexp(m0 - mn0),  a1 = fexp(m1 - mn1);

        float ls0 = 0.f, ls1 = 0.f;
        #pragma unroll
        for (int nt = 0; nt < 8; nt++) {
            s[nt][0] = rtf(fexp(s[nt][0] - mn0));
            s[nt][1] = rtf(fexp(s[nt][1] - mn0));
            s[nt][2] = rtf(fexp(s[nt][2] - mn1));
            s[nt][3] = rtf(fexp(s[nt][3] - mn1));
            ls0 += s[nt][0] + s[nt][1];
            ls1 += s[nt][2] + s[nt][3];
        }
        #pragma unroll
        for (int off = 1; off <= 2; off <<= 1) {
            ls0 += __shfl_xor_sync(0xffffffffu, ls0, off);
            ls1 += __shfl_xor_sync(0xffffffffu, ls1, off);
        }
        l0 = l0*a0 + ls0;  l1 = l1*a1 + ls1;
        m0 = mn0;          m1 = mn1;
        #pragma unroll
        for (int nt = 0; nt < 8; nt++) {
            o[nt][0] *= a0; o[nt][1] *= a0;
            o[nt][2] *= a1; o[nt][3] *= a1;
        }

        // ---- P -> smem (warp-private rows) ----
        const int pr0 = w*16 + grp;
        #pragma unroll
        for (int nt = 0; nt < 8; nt++) {
            float2 v0; v0.x = s[nt][0]; v0.y = s[nt][1];
            float2 v1; v1.x = s[nt][2]; v1.y = s[nt][3];
            *(float2*)&Ps[pr0*APAD     + nt*8 + tig*2] = v0;
            *(float2*)&Ps[(pr0+8)*APAD + nt*8 + tig*2] = v1;
        }
        __syncwarp();

        // ---- O += P V ----
        #pragma unroll
        for (int kk = 0; kk < 8; kk++) {
            uint32_t pa[4];
            pa[0] = __float_as_uint(Ps[(w*16 + grp)*APAD     + kk*8 + tig]);
            pa[1] = __float_as_uint(Ps[(w*16 + grp + 8)*APAD + kk*8 + tig]);
            pa[2] = __float_as_uint(Ps[(w*16 + grp)*APAD     + kk*8 + tig + 4]);
            pa[3] = __float_as_uint(Ps[(w*16 + grp + 8)*APAD + kk*8 + tig + 4]);
            #pragma unroll
            for (int nt = 0; nt < 8; nt++) {
                uint32_t b[2];
                b[0] = __float_as_uint(Vt[(nt*8 + grp)*APAD + kk*8 + tig]);
                b[1] = __float_as_uint(Vt[(nt*8 + grp)*APAD + kk*8 + tig + 4]);
                mma_tf32(o[nt], pa, b);
            }
        }
    }

    // ---- epilogue: ctx[b, t, h*64 + d] = O / l ----
    const int b_ = bh >> 4, h = bh & 15;
    const float inv0 = 1.0f / l0, inv1 = 1.0f / l1;
    #pragma unroll
    for (int nt = 0; nt < 8; nt++) {
        const int col = h*64 + nt*8 + tig*2;
        float2 v0; v0.x = o[nt][0]*inv0; v0.y = o[nt][1]*inv0;
        float2 v1; v1.x = o[nt][2]*inv1; v1.y = o[nt][3]*inv1;
        *(float2*)&g_ctx[((size_t)(b_*TT + r0))*EE + col] = v0;
        *(float2*)&g_ctx[((size_t)(b_*TT + r1))*EE + col] = v1;
    }
}

// ---------------------------------------------------------------------------
extern "C" void kernel_launch(void* const* d_in, const int* in_sizes, int n_in,
                              void* d_out, int out_size)
{
    const float* hs    = (const float*)d_in[0];
    const float* q_w   = (const float*)d_in[1];
    const float* q_b   = (const float*)d_in[2];
    const float* k_w   = (const float*)d_in[3];
    const float* k_b   = (const float*)d_in[4];
    const float* v_w   = (const float*)d_in[5];
    const float* v_b   = (const float*)d_in[6];
    const float* out_w = (const float*)d_in[7];
    const float* out_b = (const float*)d_in[8];
    float* out = (float*)d_out;

    cudaFuncSetAttribute(attn_mma,
                         cudaFuncAttributeMaxDynamicSharedMemorySize, ATTN_SMEM);

    // QKV projection (tf32 tensor cores)
    gemm_mma<<<dim3(24, 64), 256>>>(hs, q_w, q_b, k_w, k_b, v_w, v_b, nullptr, 0);
    // Flash attention (tf32 tensor cores + FMA-pipe exp)
    attn_mma<<<dim3(32, 64), 128, ATTN_SMEM>>>();
    // Output projection (tf32 tensor cores)
    gemm_mma<<<dim3(8, 64), 256>>>(nullptr, out_w, out_b, nullptr, nullptr,
                                   nullptr, nullptr, out, 1);
}

// round 6
// speedup vs baseline: 2.9632x; 1.0694x over previous
#include <cuda_runtime.h>
#include <math_constants.h>
#include <cstdint>

#define BB 4
#define TT 2048
#define EE 1024
#define HH 16
#define DD 64

// Scratch (device globals — no allocation allowed in kernel_launch)
__device__ float g_Q[BB*HH*TT*DD];     // [b,h,t,d]  tf32-rounded, pre-scaled 0.125
__device__ float g_K[BB*HH*TT*DD];     // [b,h,t,d]  tf32-rounded
__device__ float g_Vt[BB*HH*DD*TT];    // [b,h,d,t]  tf32-rounded, TRANSPOSED
__device__ float g_ctx[BB*TT*EE];      // tf32-rounded (attn epilogue)
__device__ float g_hsr[BB*TT*EE];      // hidden, tf32-rounded
__device__ float g_wr[4*EE*EE];        // q,k,v,out weights, tf32-rounded

// ---------------------------------------------------------------------------
// helpers
// ---------------------------------------------------------------------------
__device__ __forceinline__ uint32_t f2tf32(float x) {
    uint32_t r;
    asm("cvt.rna.tf32.f32 %0, %1;" : "=r"(r) : "f"(x));
    return r;
}
__device__ __forceinline__ float rtf(float x) { return __uint_as_float(f2tf32(x)); }

__device__ __forceinline__ uint32_t smem_u32(const void* p) {
    uint32_t a;
    asm("{ .reg .u64 t; cvta.to.shared.u64 t, %1; cvt.u32.u64 %0, t; }" : "=r"(a) : "l"(p));
    return a;
}

__device__ __forceinline__ void mma_tf32(float c[4], const uint32_t a[4], const uint32_t b[2]) {
    asm volatile(
        "mma.sync.aligned.m16n8k8.row.col.f32.tf32.tf32.f32 "
        "{%0,%1,%2,%3}, {%4,%5,%6,%7}, {%8,%9}, {%0,%1,%2,%3};"
        : "+f"(c[0]), "+f"(c[1]), "+f"(c[2]), "+f"(c[3])
        : "r"(a[0]), "r"(a[1]), "r"(a[2]), "r"(a[3]), "r"(b[0]), "r"(b[1]));
}

#define CP_ASYNC16(dst, src) \
    asm volatile("cp.async.cg.shared.global [%0], [%1], 16;" :: "r"(dst), "l"(src) : "memory")
#define CP_COMMIT() asm volatile("cp.async.commit_group;" ::: "memory")
#define CP_WAIT(n)  asm volatile("cp.async.wait_group %0;" :: "n"(n) : "memory")

// exp on the FMA pipe (no MUFU)
__device__ __forceinline__ float fexp(float x) {
    x = fmaxf(x, -80.0f);
    float y = x * 1.4426950408889634f;
    float r = rintf(y);
    float f = y - r;
    float p = 0.0013333558146428443f;
    p = fmaf(p, f, 0.009618129107628477f);
    p = fmaf(p, f, 0.05550410866482158f);
    p = fmaf(p, f, 0.2402265069591007f);
    p = fmaf(p, f, 0.6931471805599453f);
    p = fmaf(p, f, 1.0f);
    return p * __int_as_float(((int)r + 127) << 23);
}

// ---------------------------------------------------------------------------
// fp32 -> tf32-rounded fp32 (memory pass)
// ---------------------------------------------------------------------------
__global__ void round_tf32(const float* __restrict__ src, float* __restrict__ dst, int n4)
{
    int i = blockIdx.x * blockDim.x + threadIdx.x;
    if (i >= n4) return;
    float4 v = ((const float4*)src)[i];
    v.x = rtf(v.x); v.y = rtf(v.y); v.z = rtf(v.z); v.w = rtf(v.w);
    ((float4*)dst)[i] = v;
}

// ---------------------------------------------------------------------------
// tf32 tensor-core GEMM, cp.async double-buffered. Inputs pre-rounded.
// mode 0: A=g_hsr, W=g_wr[mat], scatter to g_Q/g_K/g_Vt (Q*0.125, V transposed)
// mode 1: A=g_ctx, W=g_wr[3], epilogue to Cout row-major.
// ---------------------------------------------------------------------------
#define PAD 36
#define GSTAGE (2 * 128 * PAD * 4)       // A+B tile bytes per stage = 36864
#define GEMM_SMEM (2 * GSTAGE)           // 73728

__global__ void __launch_bounds__(256)
gemm_mma(const float* __restrict__ bq, const float* __restrict__ bk,
         const float* __restrict__ bv, float* __restrict__ Cout, int mode)
{
    extern __shared__ char smc[];
    const uint32_t sb = smem_u32(smc);

    const int K = EE;
    const float* A;
    const float* W;
    const float* bias;
    float scale = 1.0f;
    int n0;
    int mat = 0;
    if (mode == 0) {
        mat = blockIdx.x >> 3;
        n0 = (blockIdx.x & 7) * 128;
        A = g_hsr;
        W = g_wr + (size_t)mat * EE * EE;
        if (mat == 0)      { bias = bq; scale = 0.125f; }
        else if (mat == 1) { bias = bk; }
        else               { bias = bv; }
    } else {
        n0 = blockIdx.x * 128;
        A = g_ctx;
        W = g_wr + (size_t)3 * EE * EE;
        bias = bq;
    }
    const int m0 = blockIdx.y * 128;

    const int tid  = threadIdx.x;
    const int wid  = tid >> 5;
    const int lane = tid & 31;
    const int grp  = lane >> 2;
    const int tig  = lane & 3;
    const int wm   = (wid & 3) * 32;
    const int wn   = (wid >> 2) * 64;

    // loader mapping: idx -> (row, 4-float seg)
    const int lr = tid >> 1;             // unused alt
    (void)lr;

    float acc[2][8][4];
    #pragma unroll
    for (int i = 0; i < 2; i++)
        #pragma unroll
        for (int j = 0; j < 8; j++)
            #pragma unroll
            for (int q = 0; q < 4; q++) acc[i][j][q] = 0.f;

    // issue cp.async for stage `buf`, k-offset ks
    auto load_stage = [&](int ks, int buf) {
        const uint32_t aoff = sb + buf * GSTAGE;
        const uint32_t boff = aoff + 128 * PAD * 4;
        #pragma unroll
        for (int it = 0; it < 4; it++) {
            int idx = tid + it * 256;         // 0..1023
            int r = idx >> 3;                 // 0..127
            int s = (idx & 7) * 4;            // 0..28
            uint32_t d = (uint32_t)(r * PAD + s) * 4;
            CP_ASYNC16(aoff + d, A + (size_t)(m0 + r) * K + ks + s);
            CP_ASYNC16(boff + d, W + (size_t)(n0 + r) * K + ks + s);
        }
        CP_COMMIT();
    };

    const int NIT = K / 32;                  // 32
    load_stage(0, 0);

    for (int t = 0; t < NIT; t++) {
        if (t + 1 < NIT) {
            load_stage((t + 1) * 32, (t + 1) & 1);
            CP_WAIT(1);
        } else {
            CP_WAIT(0);
        }
        __syncthreads();

        const uint32_t* As = (const uint32_t*)(smc + (t & 1) * GSTAGE);
        const uint32_t* Bs = As + 128 * PAD;

        #pragma unroll
        for (int kk = 0; kk < 4; kk++) {
            const int kb = kk * 8;
            uint32_t a[2][4], b[8][2];
            #pragma unroll
            for (int mt = 0; mt < 2; mt++) {
                a[mt][0] = As[(wm + mt*16 + grp    )*PAD + kb + tig];
                a[mt][1] = As[(wm + mt*16 + grp + 8)*PAD + kb + tig];
                a[mt][2] = As[(wm + mt*16 + grp    )*PAD + kb + tig + 4];
                a[mt][3] = As[(wm + mt*16 + grp + 8)*PAD + kb + tig + 4];
            }
            #pragma unroll
            for (int nt = 0; nt < 8; nt++) {
                b[nt][0] = Bs[(wn + nt*8 + grp)*PAD + kb + tig];
                b[nt][1] = Bs[(wn + nt*8 + grp)*PAD + kb + tig + 4];
            }
            #pragma unroll
            for (int mt = 0; mt < 2; mt++)
                #pragma unroll
                for (int nt = 0; nt < 8; nt++)
                    mma_tf32(acc[mt][nt], a[mt], b[nt]);
        }
        __syncthreads();
    }

    #pragma unroll
    for (int mt = 0; mt < 2; mt++) {
        #pragma unroll
        for (int half = 0; half < 2; half++) {
            const int row = m0 + wm + mt*16 + grp + half*8;
            #pragma unroll
            for (int nt = 0; nt < 8; nt++) {
                const int col = n0 + wn + nt*8 + tig*2;
                float c0 = (acc[mt][nt][half*2 + 0] + bias[col])     * scale;
                float c1 = (acc[mt][nt][half*2 + 1] + bias[col + 1]) * scale;
                if (mode == 0) {
                    int h = col >> 6, d = col & 63;
                    int b_ = row >> 11, tq = row & 2047;
                    if (mat == 2) {
                        size_t base = (((size_t)(b_*HH + h))*DD + d)*TT + tq;
                        g_Vt[base]      = rtf(c0);
                        g_Vt[base + TT] = rtf(c1);
                    } else {
                        float* qkv = (mat == 0) ? g_Q : g_K;
                        float2 v; v.x = rtf(c0); v.y = rtf(c1);
                        *(float2*)&qkv[(((size_t)(b_*HH + h))*TT + tq)*DD + d] = v;
                    }
                } else {
                    float2 v; v.x = c0; v.y = c1;
                    *(float2*)&Cout[(size_t)row * EE + col] = v;
                }
            }
        }
    }
}

// ---------------------------------------------------------------------------
// Flash attention on tf32 tensor cores, 128-row Q tile, 8 warps,
// cp.async double-buffered K/V tiles.
// ---------------------------------------------------------------------------
#define APAD 68
#define KVSTAGE (2 * 64 * APAD * 4)                // K + V per stage = 34816
#define ATTN_SMEM (2 * KVSTAGE + 128 * APAD * 4)   // 104448

__global__ void __launch_bounds__(256)
attn_mma()
{
    extern __shared__ char smc[];
    const uint32_t sb = smem_u32(smc);
    float* Ps = (float*)(smc + 2 * KVSTAGE);    // [128][APAD]

    const int bh = blockIdx.y;
    const int q0 = blockIdx.x * 128;
    const float* Qg = g_Q  + (size_t)bh*TT*DD;
    const float* Kg = g_K  + (size_t)bh*TT*DD;
    const float* Vg = g_Vt + (size_t)bh*DD*TT;

    const int tid  = threadIdx.x;
    const int lane = tid & 31;
    const int w    = tid >> 5;                  // 0..7
    const int grp  = lane >> 2;
    const int tig  = lane & 3;
    const int r0   = q0 + w*16 + grp;
    const int r1   = r0 + 8;

    // Q fragments (pre-rounded tf32 in gmem)
    uint32_t qa[8][4];
    #pragma unroll
    for (int kk = 0; kk < 8; kk++) {
        qa[kk][0] = __float_as_uint(Qg[(size_t)r0*DD + kk*8 + tig]);
        qa[kk][1] = __float_as_uint(Qg[(size_t)r1*DD + kk*8 + tig]);
        qa[kk][2] = __float_as_uint(Qg[(size_t)r0*DD + kk*8 + tig + 4]);
        qa[kk][3] = __float_as_uint(Qg[(size_t)r1*DD + kk*8 + tig + 4]);
    }

    float o[8][4];
    #pragma unroll
    for (int nt = 0; nt < 8; nt++)
        #pragma unroll
        for (int q = 0; q < 4; q++) o[nt][q] = 0.f;
    float m0 = -CUDART_INF_F, m1 = -CUDART_INF_F, l0 = 0.f, l1 = 0.f;

    // K tile (64x64) + V^T tile (64x64): 2048 float4 / 256 threads = 8 cp.async
    auto load_tile = [&](int kt, int buf) {
        const uint32_t koff = sb + buf * KVSTAGE;
        const uint32_t voff = koff + 64 * APAD * 4;
        #pragma unroll
        for (int it = 0; it < 4; it++) {
            int idx = tid + it * 256;          // 0..1023
            int r = idx >> 4;                  // 0..63
            int c = (idx & 15) * 4;            // 0..60
            uint32_t d = (uint32_t)(r * APAD + c) * 4;
            CP_ASYNC16(koff + d, Kg + (size_t)(kt + r)*DD + c);
            CP_ASYNC16(voff + d, Vg + (size_t)r*TT + kt + c);
        }
        CP_COMMIT();
    };

    const int NIT = TT / 64;                   // 32
    load_tile(0, 0);

    for (int t = 0; t < NIT; t++) {
        if (t + 1 < NIT) {
            load_tile((t + 1) * 64, (t + 1) & 1);
            CP_WAIT(1);
        } else {
            CP_WAIT(0);
        }
        __syncthreads();

        const float* Ks = (const float*)(smc + (t & 1) * KVSTAGE);
        const float* Vt = Ks + 64 * APAD;

        // ---- S = Q K^T ----
        float s[8][4];
        #pragma unroll
        for (int nt = 0; nt < 8; nt++)
            #pragma unroll
            for (int q = 0; q < 4; q++) s[nt][q] = 0.f;

        #pragma unroll
        for (int kk = 0; kk < 8; kk++) {
            #pragma unroll
            for (int nt = 0; nt < 8; nt++) {
                uint32_t b[2];
                b[0] = __float_as_uint(Ks[(nt*8 + grp)*APAD + kk*8 + tig]);
                b[1] = __float_as_uint(Ks[(nt*8 + grp)*APAD + kk*8 + tig + 4]);
                mma_tf32(s[nt], qa[kk], b);
            }
        }

        // ---- online softmax ----
        float mx0 = -CUDART_INF_F, mx1 = -CUDART_INF_F;
        #pragma unroll
        for (int nt = 0; nt < 8; nt++) {
            mx0 = fmaxf(mx0, fmaxf(s[nt][0], s[nt][1]));
            mx1 = fmaxf(mx1, fmaxf(s[nt][2], s[nt][3]));
        }
        #pragma unroll
        for (int off = 1; off <= 2; off <<= 1) {
            mx0 = fmaxf(mx0, __shfl_xor_sync(0xffffffffu, mx0, off));
            mx1 = fmaxf(mx1, __shfl_xor_sync(0xffffffffu, mx1, off));
        }
        float mn0 = fmaxf(m0, mx0), mn1 = fmaxf(m1, mx1);
        float a0 = fexp(m0 - mn0),  a1 = fexp(m1 - mn1);

        float ls0 = 0.f, ls1 = 0.f;
        #pragma unroll
        for (int nt = 0; nt < 8; nt++) {
            s[nt][0] = rtf(fexp(s[nt][0] - mn0));
            s[nt][1] = rtf(fexp(s[nt][1] - mn0));
            s[nt][2] = rtf(fexp(s[nt][2] - mn1));
            s[nt][3] = rtf(fexp(s[nt][3] - mn1));
            ls0 += s[nt][0] + s[nt][1];
            ls1 += s[nt][2] + s[nt][3];
        }
        #pragma unroll
        for (int off = 1; off <= 2; off <<= 1) {
            ls0 += __shfl_xor_sync(0xffffffffu, ls0, off);
            ls1 += __shfl_xor_sync(0xffffffffu, ls1, off);
        }
        l0 = l0*a0 + ls0;  l1 = l1*a1 + ls1;
        m0 = mn0;          m1 = mn1;
        #pragma unroll
        for (int nt = 0; nt < 8; nt++) {
            o[nt][0] *= a0; o[nt][1] *= a0;
            o[nt][2] *= a1; o[nt][3] *= a1;
        }

        // ---- P -> smem (warp-private 16 rows) ----
        const int pr0 = w*16 + grp;
        #pragma unroll
        for (int nt = 0; nt < 8; nt++) {
            float2 v0; v0.x = s[nt][0]; v0.y = s[nt][1];
            float2 v1; v1.x = s[nt][2]; v1.y = s[nt][3];
            *(float2*)&Ps[pr0*APAD     + nt*8 + tig*2] = v0;
            *(float2*)&Ps[(pr0+8)*APAD + nt*8 + tig*2] = v1;
        }
        __syncwarp();

        // ---- O += P V ----
        #pragma unroll
        for (int kk = 0; kk < 8; kk++) {
            uint32_t pa[4];
            pa[0] = __float_as_uint(Ps[(w*16 + grp)*APAD     + kk*8 + tig]);
            pa[1] = __float_as_uint(Ps[(w*16 + grp + 8)*APAD + kk*8 + tig]);
            pa[2] = __float_as_uint(Ps[(w*16 + grp)*APAD     + kk*8 + tig + 4]);
            pa[3] = __float_as_uint(Ps[(w*16 + grp + 8)*APAD + kk*8 + tig + 4]);
            #pragma unroll
            for (int nt = 0; nt < 8; nt++) {
                uint32_t b[2];
                b[0] = __float_as_uint(Vt[(nt*8 + grp)*APAD + kk*8 + tig]);
                b[1] = __float_as_uint(Vt[(nt*8 + grp)*APAD + kk*8 + tig + 4]);
                mma_tf32(o[nt], pa, b);
            }
        }
        __syncthreads();
    }

    // ---- epilogue: ctx[b, t, h*64 + d] = O / l  (tf32-rounded for out-proj) ----
    const int b_ = bh >> 4, h = bh & 15;
    const float inv0 = 1.0f / l0, inv1 = 1.0f / l1;
    #pragma unroll
    for (int nt = 0; nt < 8; nt++) {
        const int col = h*64 + nt*8 + tig*2;
        float2 v0; v0.x = rtf(o[nt][0]*inv0); v0.y = rtf(o[nt][1]*inv0);
        float2 v1; v1.x = rtf(o[nt][2]*inv1); v1.y = rtf(o[nt][3]*inv1);
        *(float2*)&g_ctx[((size_t)(b_*TT + r0))*EE + col] = v0;
        *(float2*)&g_ctx[((size_t)(b_*TT + r1))*EE + col] = v1;
    }
}

// ---------------------------------------------------------------------------
extern "C" void kernel_launch(void* const* d_in, const int* in_sizes, int n_in,
                              void* d_out, int out_size)
{
    const float* hs    = (const float*)d_in[0];
    const float* q_w   = (const float*)d_in[1];
    const float* q_b   = (const float*)d_in[2];
    const float* k_w   = (const float*)d_in[3];
    const float* k_b   = (const float*)d_in[4];
    const float* v_w   = (const float*)d_in[5];
    const float* v_b   = (const float*)d_in[6];
    const float* out_w = (const float*)d_in[7];
    const float* out_b = (const float*)d_in[8];
    float* out = (float*)d_out;

    cudaFuncSetAttribute(gemm_mma,
                         cudaFuncAttributeMaxDynamicSharedMemorySize, GEMM_SMEM);
    cudaFuncSetAttribute(attn_mma,
                         cudaFuncAttributeMaxDynamicSharedMemorySize, ATTN_SMEM);

    float *hsr, *wr;
    cudaGetSymbolAddress((void**)&hsr, g_hsr);
    cudaGetSymbolAddress((void**)&wr, g_wr);

    // pre-round inputs to valid tf32 bit patterns (RNA)
    const int n4h = BB*TT*EE/4, n4w = EE*EE/4;
    round_tf32<<<(n4h+255)/256, 256>>>(hs, hsr, n4h);
    round_tf32<<<(n4w+255)/256, 256>>>(q_w,   wr,            n4w);
    round_tf32<<<(n4w+255)/256, 256>>>(k_w,   wr +   EE*EE,  n4w);
    round_tf32<<<(n4w+255)/256, 256>>>(v_w,   wr + 2*EE*EE,  n4w);
    round_tf32<<<(n4w+255)/256, 256>>>(out_w, wr + 3*EE*EE,  n4w);

    // QKV projection (tf32, cp.async pipelined)
    gemm_mma<<<dim3(24, 64), 256, GEMM_SMEM>>>(q_b, k_b, v_b, nullptr, 0);
    // Flash attention (tf32, cp.async pipelined, 128-row Q tiles)
    attn_mma<<<dim3(16, 64), 256, ATTN_SMEM>>>();
    // Output projection
    gemm_mma<<<dim3(8, 64), 256, GEMM_SMEM>>>(out_b, nullptr, nullptr, out, 1);
}